// round 14
// baseline (speedup 1.0000x reference)
#include <cuda_runtime.h>
#include <cuda_fp16.h>
#include <cstdint>

#define NB  16
#define NC  256
#define NHW 4096

// ---------------- scratch ----------------------------------------------------
__device__ __half g_Wqkv[3 * NC * NC];
__device__ __half g_xT[(size_t)NB * NHW * NC];        // [b][n][c]
__device__ __half g_phi[(size_t)NB * 3 * NC * NHW];   // [b][q/-/v][c][n] (slot 1 unused)
__device__ __half g_phiKT[(size_t)NB * NHW * NC];     // [b][n][c]
__device__ float  g_qvp[8 * NB * NC * NC];            // split-K partials [ks][b][c][d]
__device__ __half g_M[NB * NC * NC];                  // [b][o][d], scaled by 1/16

// ---------------- helpers ---------------------------------------------------
__device__ __forceinline__ void mma16816(float* c, const uint32_t* a, const uint32_t* b) {
    asm volatile(
        "mma.sync.aligned.m16n8k16.row.col.f32.f16.f16.f32 "
        "{%0,%1,%2,%3},{%4,%5,%6,%7},{%8,%9},{%0,%1,%2,%3};\n"
        : "+f"(c[0]), "+f"(c[1]), "+f"(c[2]), "+f"(c[3])
        : "r"(a[0]), "r"(a[1]), "r"(a[2]), "r"(a[3]), "r"(b[0]), "r"(b[1]));
}
__device__ __forceinline__ float phi_f(float v) { return v > 0.0f ? v + 1.0f : __expf(v); }

__device__ __forceinline__ void cpa16(uint32_t s, const void* g) {
    asm volatile("cp.async.cg.shared.global [%0], [%1], 16;" :: "r"(s), "l"(g));
}
#define CPA_COMMIT() asm volatile("cp.async.commit_group;" ::: "memory")
#define CPA_WAIT0()  asm volatile("cp.async.wait_group 0;" ::: "memory")

#define LOAD_AFRAG(dst, S, r0, kk, P)                                   \
    do {                                                                \
        dst[0] = *(const uint32_t*)&S[(r0) * (P) + (kk)];               \
        dst[1] = *(const uint32_t*)&S[((r0) + 8) * (P) + (kk)];         \
        dst[2] = *(const uint32_t*)&S[(r0) * (P) + (kk) + 8];           \
        dst[3] = *(const uint32_t*)&S[((r0) + 8) * (P) + (kk) + 8];     \
    } while (0)
#define LOAD_BFRAG(dst, S, r0, kk, P)                                   \
    do {                                                                \
        dst[0] = *(const uint32_t*)&S[(r0) * (P) + (kk)];               \
        dst[1] = *(const uint32_t*)&S[(r0) * (P) + (kk) + 8];           \
    } while (0)

// ---------------- K0a: weight prep (fp16 QKV) --------------------------------
__global__ void prep_weights(const float* __restrict__ Wq, const float* __restrict__ Wk,
                             const float* __restrict__ Wv) {
    int i = blockIdx.x * blockDim.x + threadIdx.x;
    if (i < NC * NC) {
        g_Wqkv[i]               = __float2half_rn(Wq[i]);
        g_Wqkv[NC * NC + i]     = __float2half_rn(Wk[i]);
        g_Wqkv[2 * NC * NC + i] = __float2half_rn(Wv[i]);
    }
}

// ---------------- K0b: x[b][c][n] f32 -> g_xT[b][n][c] fp16 ------------------
__global__ void transpose_x(const float* __restrict__ x) {
    __shared__ float tile[32][33];
    int b = blockIdx.z, n0 = blockIdx.x * 32, c0 = blockIdx.y * 32;
    int tx = threadIdx.x, ty = threadIdx.y;
    const float* xb = x + (size_t)b * NC * NHW;
#pragma unroll
    for (int j = 0; j < 32; j += 8)
        tile[ty + j][tx] = xb[(size_t)(c0 + ty + j) * NHW + n0 + tx];
    __syncthreads();
    __half* o = g_xT + (size_t)b * NHW * NC;
#pragma unroll
    for (int j = 0; j < 32; j += 8)
        o[(size_t)(n0 + ty + j) * NC + c0 + tx] = __float2half_rn(tile[tx][ty + j]);
}

// ---------------- K1: proj v3 — x-tile resident, W streamed ------------------
// Block = (nt, b): x tile [128n][264p] resident; mt=0..5 W slices double-buffered.
// mt 0,1 -> phiQ ; mt 4,5 -> phiV (normal A=W, B=x, D[c][n]);
// mt 2,3 -> phiKT (swapped A=x, B=W, D'[n][c], row-contiguous stores).
#define PROJ_X_BYTES (128 * 264 * 2)                 // 67584
#define PROJ_W_BYTES (128 * 40 * 2)                  // 10240 per stage
#define PROJ_SMEM    (PROJ_X_BYTES + 2 * PROJ_W_BYTES)
__global__ __launch_bounds__(256, 2) void proj_kernel() {
    extern __shared__ __align__(16) char raw[];
    const int b = blockIdx.y, nt = blockIdx.x;
    const int t = threadIdx.x, warp = t >> 5, lane = t & 31;
    const int wm = (warp >> 1) * 32, wn = (warp & 1) * 64;
    const int fr = lane >> 2, fc = (lane & 3) * 2;
    const int lr = t >> 2, lc = (t & 3) * 8;

    const __half* Bg = g_xT + ((size_t)b * NHW + nt * 128) * NC;
    uint32_t raw_s = (uint32_t)__cvta_generic_to_shared(raw);
    const __half* sX = (const __half*)raw;           // [128][264]

    // x tile: 16 cp.async per thread (whole K=256)
#pragma unroll
    for (int i = 0; i < 16; i++) {
        int idx = t + i * 256;
        int r = idx >> 5, cc = (idx & 31) * 8;
        cpa16(raw_s + (r * 264 + cc) * 2, Bg + (size_t)r * NC + cc);
    }
    auto issueW = [&](int s, int mt, int k0) {
        uint32_t base = raw_s + PROJ_X_BYTES + s * PROJ_W_BYTES;
        const __half* Ag = g_Wqkv + (size_t)(mt * 128) * NC;
#pragma unroll
        for (int i = 0; i < 2; i++) {
            int r = lr + i * 64;
            cpa16(base + (r * 40 + lc) * 2, Ag + (size_t)r * NC + k0 + lc);
        }
    };
    issueW(0, 0, 0); CPA_COMMIT();

    float acc[2][8][4] = {};
    for (int it = 0; it < 48; it++) {
        CPA_WAIT0();
        __syncthreads();
        if (it < 47) { issueW((it + 1) & 1, (it + 1) >> 3, ((it + 1) & 7) * 32); CPA_COMMIT(); }
        const int mt = it >> 3, kg = (it & 7) * 32;
        const bool swap = (mt == 2 || mt == 3);
        const __half* sW = (const __half*)(raw + PROJ_X_BYTES + (it & 1) * PROJ_W_BYTES);
#pragma unroll
        for (int ks = 0; ks < 32; ks += 16) {
            uint32_t a[2][4];
            if (swap) {
                LOAD_AFRAG(a[0], sX, wm + fr, kg + ks + fc, 264);
                LOAD_AFRAG(a[1], sX, wm + 16 + fr, kg + ks + fc, 264);
#pragma unroll
                for (int ni = 0; ni < 8; ni++) {
                    uint32_t bb[2];
                    LOAD_BFRAG(bb, sW, wn + ni * 8 + fr, ks + fc, 40);
                    mma16816(acc[0][ni], a[0], bb);
                    mma16816(acc[1][ni], a[1], bb);
                }
            } else {
                LOAD_AFRAG(a[0], sW, wm + fr, ks + fc, 40);
                LOAD_AFRAG(a[1], sW, wm + 16 + fr, ks + fc, 40);
#pragma unroll
                for (int ni = 0; ni < 8; ni++) {
                    uint32_t bb[2];
                    LOAD_BFRAG(bb, sX, wn + ni * 8 + fr, kg + ks + fc, 264);
                    mma16816(acc[0][ni], a[0], bb);
                    mma16816(acc[1][ni], a[1], bb);
                }
            }
        }
        if ((it & 7) == 7) {
            // epilogue for slice mt (regs -> gmem only; no smem, no extra sync)
            if (swap) {
#pragma unroll
                for (int mi = 0; mi < 2; mi++)
#pragma unroll
                    for (int half = 0; half < 2; half++) {
                        int n = nt * 128 + wm + mi * 16 + fr + half * 8;
                        __half* dst = g_phiKT + ((size_t)b * NHW + n) * NC + (mt - 2) * 128;
#pragma unroll
                        for (int ni = 0; ni < 8; ni++) {
                            int c = wn + ni * 8 + fc;
                            *(__half2*)&dst[c] = __floats2half2_rn(
                                phi_f(acc[mi][ni][half * 2 + 0]),
                                phi_f(acc[mi][ni][half * 2 + 1]));
                        }
                    }
            } else {
#pragma unroll
                for (int mi = 0; mi < 2; mi++)
#pragma unroll
                    for (int half = 0; half < 2; half++) {
                        int gr = mt * 128 + wm + mi * 16 + fr + half * 8;
                        int which = gr >> 8, cc = gr & 255;
                        __half* dst = g_phi + (((size_t)b * 3 + which) * NC + cc) * NHW;
#pragma unroll
                        for (int ni = 0; ni < 8; ni++) {
                            int gn = nt * 128 + wn + ni * 8 + fc;
                            *(__half2*)&dst[gn] = __floats2half2_rn(
                                phi_f(acc[mi][ni][half * 2 + 0]),
                                phi_f(acc[mi][ni][half * 2 + 1]));
                        }
                    }
            }
#pragma unroll
            for (int i = 0; i < 2; i++)
#pragma unroll
                for (int j = 0; j < 8; j++)
#pragma unroll
                    for (int k = 0; k < 4; k++) acc[i][j][k] = 0.0f;
        }
    }
}

// ---------------- K2: qv split-K=8, 128x64 block / 32x32 warp tile -----------
#define QV_SMEM (2 * 27648)
__global__ __launch_bounds__(256) void qv_kernel() {
    extern __shared__ __align__(16) char raw[];     // 2 x (sA 128x72 | sB 64x72)
    const int dt = blockIdx.x, ct = blockIdx.y;
    const int b = blockIdx.z >> 3, ks = blockIdx.z & 7;
    const int t = threadIdx.x, warp = t >> 5, lane = t & 31;
    const int wm = (warp >> 1) * 32, wn = (warp & 1) * 32;
    const int fr = lane >> 2, fc = (lane & 3) * 2;
    const int lr = t >> 3, lc = (t & 7) * 8;

    float acc[2][4][4] = {};
    const __half* Ag = g_phi + (((size_t)b * 3 + 0) * NC + ct * 128) * NHW;
    const __half* Bg = g_phi + (((size_t)b * 3 + 2) * NC + dt * 64) * NHW;
    uint32_t raw_s = (uint32_t)__cvta_generic_to_shared(raw);

    auto issue = [&](int s, int k0) {
        uint32_t base = raw_s + s * 27648;
#pragma unroll
        for (int i = 0; i < 4; i++) {
            int r = lr + i * 32;
            cpa16(base + (r * 72 + lc) * 2, Ag + (size_t)r * NHW + k0 + lc);
        }
#pragma unroll
        for (int i = 0; i < 2; i++) {
            int r = lr + i * 32;
            cpa16(base + 18432 + (r * 72 + lc) * 2, Bg + (size_t)r * NHW + k0 + lc);
        }
    };

    const int kbase = ks * 512;
    issue(0, kbase); CPA_COMMIT();
    for (int it = 0; it < 8; it++) {
        CPA_WAIT0();
        __syncthreads();
        if (it < 7) { issue((it + 1) & 1, kbase + (it + 1) * 64); CPA_COMMIT(); }
        const __half* sA = (const __half*)(raw + (it & 1) * 27648);
        const __half* sB = sA + 9216;
#pragma unroll
        for (int kk = 0; kk < 64; kk += 16) {
            uint32_t a[2][4];
            LOAD_AFRAG(a[0], sA, wm + fr, kk + fc, 72);
            LOAD_AFRAG(a[1], sA, wm + 16 + fr, kk + fc, 72);
#pragma unroll
            for (int ni = 0; ni < 4; ni++) {
                uint32_t bb[2];
                LOAD_BFRAG(bb, sB, wn + ni * 8 + fr, kk + fc, 72);
                mma16816(acc[0][ni], a[0], bb);
                mma16816(acc[1][ni], a[1], bb);
            }
        }
    }

    float* dst = g_qvp + ((size_t)(ks * NB + b) * NC) * NC;
#pragma unroll
    for (int mi = 0; mi < 2; mi++)
#pragma unroll
        for (int ni = 0; ni < 4; ni++)
#pragma unroll
            for (int half = 0; half < 2; half++) {
                int c = ct * 128 + wm + mi * 16 + fr + half * 8;
                int d = dt * 64 + wn + ni * 8 + fc;
                float2 v;
                v.x = acc[mi][ni][half * 2 + 0];
                v.y = acc[mi][ni][half * 2 + 1];
                *(float2*)&dst[(size_t)c * NC + d] = v;
            }
}

// ---------------- K2.5: M = (Wo * sum_ks qvp)/16, fp16 output ----------------
__global__ __launch_bounds__(256) void mwo_kernel(const float* __restrict__ Wo) {
    __shared__ float sWo[16 * 256];
    const int b = blockIdx.x, o0 = blockIdx.y * 16;
    const int t = threadIdx.x;
#pragma unroll
    for (int i = 0; i < 16; i++)
        sWo[t + i * 256] = Wo[(size_t)(o0 + (t + i * 256) / 256) * NC + ((t + i * 256) & 255)];
    __syncthreads();

    const size_t stride = (size_t)NB * NC * NC;
    const float* q0 = g_qvp + (size_t)b * NC * NC;
    float acc[16] = {};
    for (int c = 0; c < NC; c++) {
        size_t off = (size_t)c * NC + t;
        float q = ((q0[off] + q0[stride + off]) + (q0[2 * stride + off] + q0[3 * stride + off]))
                + ((q0[4 * stride + off] + q0[5 * stride + off]) +
                   (q0[6 * stride + off] + q0[7 * stride + off]));
#pragma unroll
        for (int o = 0; o < 16; o++) acc[o] = fmaf(sWo[o * 256 + c], q, acc[o]);
    }
#pragma unroll
    for (int o = 0; o < 16; o++)
        g_M[((size_t)b * NC + o0 + o) * NC + t] = __float2half_rn(acc[o] * 0.0625f);
}

// ---------------- K3: out = 16 * (M * phiK^T) + bo (cp.async pipelined) ------
__global__ __launch_bounds__(256) void out_kernel(const float* __restrict__ bo,
                                                  float* __restrict__ out) {
    __shared__ __align__(16) char raw[40960];   // 2 x (sA 128x40 | sB 128x40)
    const int b = blockIdx.z, ot = blockIdx.y, nt = blockIdx.x;
    const int t = threadIdx.x, warp = t >> 5, lane = t & 31;
    const int wm = (warp >> 1) * 32, wn = (warp & 1) * 64;
    const int fr = lane >> 2, fc = (lane & 3) * 2;
    const int lr = t >> 2, lc = (t & 3) * 8;

    float acc[2][8][4] = {};
    const __half* Ag = g_M + ((size_t)b * NC + ot * 128) * NC;
    const __half* Bg = g_phiKT + ((size_t)b * NHW + nt * 128) * NC;
    uint32_t raw_s = (uint32_t)__cvta_generic_to_shared(raw);

    auto issue = [&](int s, int k0) {
        uint32_t base = raw_s + s * 20480;
#pragma unroll
        for (int i = 0; i < 2; i++) {
            int r = lr + i * 64;
            cpa16(base + (r * 40 + lc) * 2, Ag + (size_t)r * NC + k0 + lc);
            cpa16(base + 10240 + (r * 40 + lc) * 2, Bg + (size_t)r * NC + k0 + lc);
        }
    };

    issue(0, 0); CPA_COMMIT();
    for (int it = 0; it < 8; it++) {
        CPA_WAIT0();
        __syncthreads();
        if (it < 7) { issue((it + 1) & 1, (it + 1) * 32); CPA_COMMIT(); }
        const __half* sA = (const __half*)(raw + (it & 1) * 20480);
        const __half* sB = sA + 5120;
#pragma unroll
        for (int ks = 0; ks < 32; ks += 16) {
            uint32_t a[2][4];
            LOAD_AFRAG(a[0], sA, wm + fr, ks + fc, 40);
            LOAD_AFRAG(a[1], sA, wm + 16 + fr, ks + fc, 40);
#pragma unroll
            for (int ni = 0; ni < 8; ni++) {
                uint32_t bb[2];
                LOAD_BFRAG(bb, sB, wn + ni * 8 + fr, ks + fc, 40);
                mma16816(acc[0][ni], a[0], bb);
                mma16816(acc[1][ni], a[1], bb);
            }
        }
    }

#pragma unroll
    for (int mi = 0; mi < 2; mi++)
#pragma unroll
        for (int half = 0; half < 2; half++) {
            int o = ot * 128 + wm + mi * 16 + fr + half * 8;
            float bias = bo[o];
            float* orow = out + ((size_t)b * NC + o) * NHW;
#pragma unroll
            for (int ni = 0; ni < 8; ni++) {
                int gn = nt * 128 + wn + ni * 8 + fc;
                float2 v;
                v.x = acc[mi][ni][half * 2 + 0] * 16.0f + bias;
                v.y = acc[mi][ni][half * 2 + 1] * 16.0f + bias;
                *(float2*)&orow[gn] = v;
            }
        }
}

// ---------------- launch -----------------------------------------------------
extern "C" void kernel_launch(void* const* d_in, const int* in_sizes, int n_in,
                              void* d_out, int out_size) {
    (void)in_sizes; (void)n_in; (void)out_size;
    const float* x  = (const float*)d_in[0];
    const float* Wq = (const float*)d_in[1];
    const float* Wk = (const float*)d_in[2];
    const float* Wv = (const float*)d_in[3];
    const float* Wo = (const float*)d_in[4];
    const float* bo = (const float*)d_in[5];
    float* out = (float*)d_out;

    // Idempotent, capture-safe, no static guards.
    cudaFuncSetAttribute(qv_kernel, cudaFuncAttributeMaxDynamicSharedMemorySize, QV_SMEM);
    cudaFuncSetAttribute(proj_kernel, cudaFuncAttributeMaxDynamicSharedMemorySize, PROJ_SMEM);

    prep_weights<<<(NC * NC + 255) / 256, 256>>>(Wq, Wk, Wv);
    transpose_x<<<dim3(NHW / 32, NC / 32, NB), dim3(32, 8)>>>(x);
    proj_kernel<<<dim3(NHW / 128, NB), 256, PROJ_SMEM>>>();
    qv_kernel<<<dim3(NC / 64, NC / 128, NB * 8), 256, QV_SMEM>>>();
    mwo_kernel<<<dim3(NB, 16), 256>>>(Wo);
    out_kernel<<<dim3(NHW / 128, NC / 128, NB), 256>>>(bo, out);
}

// round 15
// speedup vs baseline: 1.0965x; 1.0965x over previous
#include <cuda_runtime.h>
#include <cuda_fp16.h>
#include <cstdint>

#define NB  16
#define NC  256
#define NHW 4096

// ---------------- scratch ----------------------------------------------------
__device__ __half g_Wqkv[3 * NC * NC];
__device__ __half g_xT[(size_t)NB * NHW * NC];        // [b][n][c]
__device__ __half g_phi[(size_t)NB * 3 * NC * NHW];   // [b][q/-/v][c][n] (slot 1 unused)
__device__ __half g_phiKT[(size_t)NB * NHW * NC];     // [b][n][c]
__device__ float  g_qvp[8 * NB * NC * NC];            // split-K partials [ks][b][c][d]
__device__ __half g_M[NB * NC * NC];                  // [b][o][d], scaled by 1/16

// ---------------- helpers ---------------------------------------------------
__device__ __forceinline__ void mma16816(float* c, const uint32_t* a, const uint32_t* b) {
    asm volatile(
        "mma.sync.aligned.m16n8k16.row.col.f32.f16.f16.f32 "
        "{%0,%1,%2,%3},{%4,%5,%6,%7},{%8,%9},{%0,%1,%2,%3};\n"
        : "+f"(c[0]), "+f"(c[1]), "+f"(c[2]), "+f"(c[3])
        : "r"(a[0]), "r"(a[1]), "r"(a[2]), "r"(a[3]), "r"(b[0]), "r"(b[1]));
}
__device__ __forceinline__ float phi_f(float v) { return v > 0.0f ? v + 1.0f : __expf(v); }

__device__ __forceinline__ void cpa16(uint32_t s, const void* g) {
    asm volatile("cp.async.cg.shared.global [%0], [%1], 16;" :: "r"(s), "l"(g));
}
#define CPA_COMMIT() asm volatile("cp.async.commit_group;" ::: "memory")
#define CPA_WAIT0()  asm volatile("cp.async.wait_group 0;" ::: "memory")

// ldmatrix x4: d0..d3 = four 8x8 b16 matrices; per-lane row addresses.
#define LDSM4(d, addr)                                                       \
    asm volatile("ldmatrix.sync.aligned.m8n8.x4.shared.b16 {%0,%1,%2,%3}, [%4];" \
        : "=r"((d)[0]), "=r"((d)[1]), "=r"((d)[2]), "=r"((d)[3]) : "r"(addr))

// Per-lane byte offsets (pitch P in halves):
//  A-frag (d0..d3 = (r0,k),(r0+8,k),(r0,k+8),(r0+8,k+8)):
//   g=lane>>3: rows += (g&1)*8, cols += (g>>1)*8
//  B-pair (d0,d1 = ni rows r0..r0+7 cols k,k+8 ; d2,d3 = rows r0+8..15):
//   rows += (g>>1)*8, cols += (g&1)*8
#define OFF_A(P) ((((g & 1) * 8 + ri) * (P) + (g >> 1) * 8) * 2)
#define OFF_B(P) ((((g >> 1) * 8 + ri) * (P) + (g & 1) * 8) * 2)

// ---------------- K0a: weight prep (fp16 QKV) --------------------------------
__global__ void prep_weights(const float* __restrict__ Wq, const float* __restrict__ Wk,
                             const float* __restrict__ Wv) {
    int i = blockIdx.x * blockDim.x + threadIdx.x;
    if (i < NC * NC) {
        g_Wqkv[i]               = __float2half_rn(Wq[i]);
        g_Wqkv[NC * NC + i]     = __float2half_rn(Wk[i]);
        g_Wqkv[2 * NC * NC + i] = __float2half_rn(Wv[i]);
    }
}

// ---------------- K0b: x[b][c][n] f32 -> g_xT[b][n][c] fp16 ------------------
__global__ void transpose_x(const float* __restrict__ x) {
    __shared__ float tile[32][33];
    int b = blockIdx.z, n0 = blockIdx.x * 32, c0 = blockIdx.y * 32;
    int tx = threadIdx.x, ty = threadIdx.y;
    const float* xb = x + (size_t)b * NC * NHW;
#pragma unroll
    for (int j = 0; j < 32; j += 8)
        tile[ty + j][tx] = xb[(size_t)(c0 + ty + j) * NHW + n0 + tx];
    __syncthreads();
    __half* o = g_xT + (size_t)b * NHW * NC;
#pragma unroll
    for (int j = 0; j < 32; j += 8)
        o[(size_t)(n0 + ty + j) * NC + c0 + tx] = __float2half_rn(tile[tx][ty + j]);
}

// ---------------- K1: QKV projection + phi (R13 structure + ldmatrix) --------
__global__ __launch_bounds__(256) void proj_kernel() {
    __shared__ __align__(16) char raw[40960];
    const int b = blockIdx.z, mt = blockIdx.y, nt = blockIdx.x;
    const int t = threadIdx.x, warp = t >> 5, lane = t & 31;
    const int wm = (warp >> 1) * 32, wn = (warp & 1) * 64;
    const int fr = lane >> 2, fc = (lane & 3) * 2;
    const int lr = t >> 2, lc = (t & 3) * 8;
    const int g = lane >> 3, ri = lane & 7;
    const uint32_t offA = OFF_A(40), offB = OFF_B(40);

    float acc[2][8][4] = {};
    const __half* Ag = g_Wqkv + (size_t)(mt * 128) * NC;
    const __half* Bg = g_xT + ((size_t)b * NHW + nt * 128) * NC;
    uint32_t raw_s = (uint32_t)__cvta_generic_to_shared(raw);

    auto issue = [&](int s, int k0) {
        uint32_t base = raw_s + s * 20480;
#pragma unroll
        for (int i = 0; i < 2; i++) {
            int r = lr + i * 64;
            cpa16(base + (r * 40 + lc) * 2, Ag + (size_t)r * NC + k0 + lc);
            cpa16(base + 10240 + (r * 40 + lc) * 2, Bg + (size_t)r * NC + k0 + lc);
        }
    };

    issue(0, 0); CPA_COMMIT();
    for (int it = 0; it < 8; it++) {
        CPA_WAIT0();
        __syncthreads();
        if (it < 7) { issue((it + 1) & 1, (it + 1) * 32); CPA_COMMIT(); }
        uint32_t sA_u = raw_s + (it & 1) * 20480;
        uint32_t sB_u = sA_u + 10240;
#pragma unroll
        for (int ks = 0; ks < 32; ks += 16) {
            uint32_t a0[4], a1[4];
            LDSM4(a0, sA_u + (wm * 40 + ks) * 2 + offA);
            LDSM4(a1, sA_u + ((wm + 16) * 40 + ks) * 2 + offA);
#pragma unroll
            for (int p = 0; p < 4; p++) {
                uint32_t bb[4];
                LDSM4(bb, sB_u + ((wn + p * 16) * 40 + ks) * 2 + offB);
                mma16816(acc[0][2 * p], a0, bb);
                mma16816(acc[1][2 * p], a1, bb);
                mma16816(acc[0][2 * p + 1], a0, bb + 2);
                mma16816(acc[1][2 * p + 1], a1, bb + 2);
            }
        }
    }
    __syncthreads();

    if (mt == 2 || mt == 3) {
        __half* st = (__half*)raw;   // [128 n][136 pitch] staging for transpose
#pragma unroll
        for (int mi = 0; mi < 2; mi++)
#pragma unroll
            for (int ni = 0; ni < 8; ni++)
#pragma unroll
                for (int e = 0; e < 4; e++) {
                    int c = wm + mi * 16 + fr + (e >> 1) * 8;
                    int n = wn + ni * 8 + fc + (e & 1);
                    st[n * 136 + c] = __float2half_rn(phi_f(acc[mi][ni][e]));
                }
        __syncthreads();
        __half* dstb = g_phiKT + ((size_t)b * NHW + nt * 128) * NC + (mt - 2) * 128;
        for (int idx = t; idx < 128 * 16; idx += 256) {
            int nl = idx >> 4, ch = (idx & 15) * 8;
            *(uint4*)&dstb[(size_t)nl * NC + ch] = *(const uint4*)&st[nl * 136 + ch];
        }
    } else {
#pragma unroll
        for (int mi = 0; mi < 2; mi++) {
#pragma unroll
            for (int half = 0; half < 2; half++) {
                int gr = mt * 128 + wm + mi * 16 + fr + half * 8;
                int which = gr >> 8, cc = gr & 255;
                __half* dst = g_phi + (((size_t)b * 3 + which) * NC + cc) * NHW;
#pragma unroll
                for (int ni = 0; ni < 8; ni++) {
                    int gn = nt * 128 + wn + ni * 8 + fc;
                    *(__half2*)&dst[gn] = __floats2half2_rn(
                        phi_f(acc[mi][ni][half * 2 + 0]), phi_f(acc[mi][ni][half * 2 + 1]));
                }
            }
        }
    }
}

// ---------------- K2: qv split-K=8, 128x64 block / 32x32 warp tile -----------
#define QV_SMEM (2 * 27648)
__global__ __launch_bounds__(256) void qv_kernel() {
    extern __shared__ __align__(16) char raw[];     // 2 x (sA 128x72 | sB 64x72)
    const int dt = blockIdx.x, ct = blockIdx.y;
    const int b = blockIdx.z >> 3, ks = blockIdx.z & 7;
    const int t = threadIdx.x, warp = t >> 5, lane = t & 31;
    const int wm = (warp >> 1) * 32, wn = (warp & 1) * 32;
    const int fr = lane >> 2, fc = (lane & 3) * 2;
    const int lr = t >> 3, lc = (t & 7) * 8;
    const int g = lane >> 3, ri = lane & 7;
    const uint32_t offA = OFF_A(72), offB = OFF_B(72);

    float acc[2][4][4] = {};
    const __half* Ag = g_phi + (((size_t)b * 3 + 0) * NC + ct * 128) * NHW;
    const __half* Bg = g_phi + (((size_t)b * 3 + 2) * NC + dt * 64) * NHW;
    uint32_t raw_s = (uint32_t)__cvta_generic_to_shared(raw);

    auto issue = [&](int s, int k0) {
        uint32_t base = raw_s + s * 27648;
#pragma unroll
        for (int i = 0; i < 4; i++) {
            int r = lr + i * 32;
            cpa16(base + (r * 72 + lc) * 2, Ag + (size_t)r * NHW + k0 + lc);
        }
#pragma unroll
        for (int i = 0; i < 2; i++) {
            int r = lr + i * 32;
            cpa16(base + 18432 + (r * 72 + lc) * 2, Bg + (size_t)r * NHW + k0 + lc);
        }
    };

    const int kbase = ks * 512;
    issue(0, kbase); CPA_COMMIT();
    for (int it = 0; it < 8; it++) {
        CPA_WAIT0();
        __syncthreads();
        if (it < 7) { issue((it + 1) & 1, kbase + (it + 1) * 64); CPA_COMMIT(); }
        uint32_t sA_u = raw_s + (it & 1) * 27648;
        uint32_t sB_u = sA_u + 18432;
#pragma unroll
        for (int kk = 0; kk < 64; kk += 16) {
            uint32_t a0[4], a1[4];
            LDSM4(a0, sA_u + (wm * 72 + kk) * 2 + offA);
            LDSM4(a1, sA_u + ((wm + 16) * 72 + kk) * 2 + offA);
#pragma unroll
            for (int p = 0; p < 2; p++) {
                uint32_t bb[4];
                LDSM4(bb, sB_u + ((wn + p * 16) * 72 + kk) * 2 + offB);
                mma16816(acc[0][2 * p], a0, bb);
                mma16816(acc[1][2 * p], a1, bb);
                mma16816(acc[0][2 * p + 1], a0, bb + 2);
                mma16816(acc[1][2 * p + 1], a1, bb + 2);
            }
        }
    }

    float* dst = g_qvp + ((size_t)(ks * NB + b) * NC) * NC;
#pragma unroll
    for (int mi = 0; mi < 2; mi++)
#pragma unroll
        for (int ni = 0; ni < 4; ni++)
#pragma unroll
            for (int half = 0; half < 2; half++) {
                int c = ct * 128 + wm + mi * 16 + fr + half * 8;
                int d = dt * 64 + wn + ni * 8 + fc;
                float2 v;
                v.x = acc[mi][ni][half * 2 + 0];
                v.y = acc[mi][ni][half * 2 + 1];
                *(float2*)&dst[(size_t)c * NC + d] = v;
            }
}

// ---------------- K2.5: M = (Wo * sum_ks qvp)/16, fp16 output ----------------
__global__ __launch_bounds__(256) void mwo_kernel(const float* __restrict__ Wo) {
    __shared__ float sWo[16 * 256];
    const int b = blockIdx.x, o0 = blockIdx.y * 16;
    const int t = threadIdx.x;
#pragma unroll
    for (int i = 0; i < 16; i++)
        sWo[t + i * 256] = Wo[(size_t)(o0 + (t + i * 256) / 256) * NC + ((t + i * 256) & 255)];
    __syncthreads();

    const size_t stride = (size_t)NB * NC * NC;
    const float* q0 = g_qvp + (size_t)b * NC * NC;
    float acc[16] = {};
    for (int c = 0; c < NC; c++) {
        size_t off = (size_t)c * NC + t;
        float q = ((q0[off] + q0[stride + off]) + (q0[2 * stride + off] + q0[3 * stride + off]))
                + ((q0[4 * stride + off] + q0[5 * stride + off]) +
                   (q0[6 * stride + off] + q0[7 * stride + off]));
#pragma unroll
        for (int o = 0; o < 16; o++) acc[o] = fmaf(sWo[o * 256 + c], q, acc[o]);
    }
#pragma unroll
    for (int o = 0; o < 16; o++)
        g_M[((size_t)b * NC + o0 + o) * NC + t] = __float2half_rn(acc[o] * 0.0625f);
}

// ---------------- K3: out = 16 * (M * phiK^T) + bo (ldmatrix + cp.async) -----
__global__ __launch_bounds__(256) void out_kernel(const float* __restrict__ bo,
                                                  float* __restrict__ out) {
    __shared__ __align__(16) char raw[40960];   // 2 x (sA 128x40 | sB 128x40)
    const int b = blockIdx.z, ot = blockIdx.y, nt = blockIdx.x;
    const int t = threadIdx.x, warp = t >> 5, lane = t & 31;
    const int wm = (warp >> 1) * 32, wn = (warp & 1) * 64;
    const int fr = lane >> 2, fc = (lane & 3) * 2;
    const int lr = t >> 2, lc = (t & 3) * 8;
    const int g = lane >> 3, ri = lane & 7;
    const uint32_t offA = OFF_A(40), offB = OFF_B(40);

    float acc[2][8][4] = {};
    const __half* Ag = g_M + ((size_t)b * NC + ot * 128) * NC;
    const __half* Bg = g_phiKT + ((size_t)b * NHW + nt * 128) * NC;
    uint32_t raw_s = (uint32_t)__cvta_generic_to_shared(raw);

    auto issue = [&](int s, int k0) {
        uint32_t base = raw_s + s * 20480;
#pragma unroll
        for (int i = 0; i < 2; i++) {
            int r = lr + i * 64;
            cpa16(base + (r * 40 + lc) * 2, Ag + (size_t)r * NC + k0 + lc);
            cpa16(base + 10240 + (r * 40 + lc) * 2, Bg + (size_t)r * NC + k0 + lc);
        }
    };

    issue(0, 0); CPA_COMMIT();
    for (int it = 0; it < 8; it++) {
        CPA_WAIT0();
        __syncthreads();
        if (it < 7) { issue((it + 1) & 1, (it + 1) * 32); CPA_COMMIT(); }
        uint32_t sA_u = raw_s + (it & 1) * 20480;
        uint32_t sB_u = sA_u + 10240;
#pragma unroll
        for (int ks = 0; ks < 32; ks += 16) {
            uint32_t a0[4], a1[4];
            LDSM4(a0, sA_u + (wm * 40 + ks) * 2 + offA);
            LDSM4(a1, sA_u + ((wm + 16) * 40 + ks) * 2 + offA);
#pragma unroll
            for (int p = 0; p < 4; p++) {
                uint32_t bb[4];
                LDSM4(bb, sB_u + ((wn + p * 16) * 40 + ks) * 2 + offB);
                mma16816(acc[0][2 * p], a0, bb);
                mma16816(acc[1][2 * p], a1, bb);
                mma16816(acc[0][2 * p + 1], a0, bb + 2);
                mma16816(acc[1][2 * p + 1], a1, bb + 2);
            }
        }
    }

#pragma unroll
    for (int mi = 0; mi < 2; mi++)
#pragma unroll
        for (int half = 0; half < 2; half++) {
            int o = ot * 128 + wm + mi * 16 + fr + half * 8;
            float bias = bo[o];
            float* orow = out + ((size_t)b * NC + o) * NHW;
#pragma unroll
            for (int ni = 0; ni < 8; ni++) {
                int gn = nt * 128 + wn + ni * 8 + fc;
                float2 v;
                v.x = acc[mi][ni][half * 2 + 0] * 16.0f + bias;
                v.y = acc[mi][ni][half * 2 + 1] * 16.0f + bias;
                *(float2*)&orow[gn] = v;
            }
        }
}

// ---------------- launch -----------------------------------------------------
extern "C" void kernel_launch(void* const* d_in, const int* in_sizes, int n_in,
                              void* d_out, int out_size) {
    (void)in_sizes; (void)n_in; (void)out_size;
    const float* x  = (const float*)d_in[0];
    const float* Wq = (const float*)d_in[1];
    const float* Wk = (const float*)d_in[2];
    const float* Wv = (const float*)d_in[3];
    const float* Wo = (const float*)d_in[4];
    const float* bo = (const float*)d_in[5];
    float* out = (float*)d_out;

    // Idempotent, capture-safe, no static guard.
    cudaFuncSetAttribute(qv_kernel, cudaFuncAttributeMaxDynamicSharedMemorySize, QV_SMEM);

    prep_weights<<<(NC * NC + 255) / 256, 256>>>(Wq, Wk, Wv);
    transpose_x<<<dim3(NHW / 32, NC / 32, NB), dim3(32, 8)>>>(x);
    proj_kernel<<<dim3(NHW / 128, 768 / 128, NB), 256>>>();
    qv_kernel<<<dim3(NC / 64, NC / 128, NB * 8), 256, QV_SMEM>>>();
    mwo_kernel<<<dim3(NB, 16), 256>>>(Wo);
    out_kernel<<<dim3(NHW / 128, NC / 128, NB), 256>>>(bo, out);
}

// round 16
// speedup vs baseline: 1.1510x; 1.0497x over previous
#include <cuda_runtime.h>
#include <cuda_fp16.h>
#include <cstdint>

#define NB  16
#define NC  256
#define NHW 4096

// ---------------- scratch ----------------------------------------------------
__device__ __half g_Wqkv[3 * NC * NC];
__device__ __half g_xT[(size_t)NB * NHW * NC];        // [b][n][c]
__device__ __half g_phi[(size_t)NB * 3 * NC * NHW];   // [b][q/-/v][c][n] (slot 1 unused)
__device__ __half g_phiKT[(size_t)NB * NHW * NC];     // [b][n][c]
__device__ float  g_qvp[8 * NB * NC * NC];            // split-K partials [ks][b][c][d]
__device__ __half g_M[NB * NC * NC];                  // [b][o][d], scaled by 1/16

// ---------------- helpers ---------------------------------------------------
__device__ __forceinline__ void mma16816(float* c, const uint32_t* a, const uint32_t* b) {
    asm volatile(
        "mma.sync.aligned.m16n8k16.row.col.f32.f16.f16.f32 "
        "{%0,%1,%2,%3},{%4,%5,%6,%7},{%8,%9},{%0,%1,%2,%3};\n"
        : "+f"(c[0]), "+f"(c[1]), "+f"(c[2]), "+f"(c[3])
        : "r"(a[0]), "r"(a[1]), "r"(a[2]), "r"(a[3]), "r"(b[0]), "r"(b[1]));
}
__device__ __forceinline__ float phi_f(float v) { return v > 0.0f ? v + 1.0f : __expf(v); }

__device__ __forceinline__ void cpa16(uint32_t s, const void* g) {
    asm volatile("cp.async.cg.shared.global [%0], [%1], 16;" :: "r"(s), "l"(g));
}
#define CPA_COMMIT() asm volatile("cp.async.commit_group;" ::: "memory")
#define CPA_WAIT0()  asm volatile("cp.async.wait_group 0;" ::: "memory")
#define CPA_WAIT1()  asm volatile("cp.async.wait_group 1;" ::: "memory")

#define LDSM4(d, addr)                                                       \
    asm volatile("ldmatrix.sync.aligned.m8n8.x4.shared.b16 {%0,%1,%2,%3}, [%4];" \
        : "=r"((d)[0]), "=r"((d)[1]), "=r"((d)[2]), "=r"((d)[3]) : "r"(addr))

// Per-lane byte offsets (pitch P in halves):
#define OFF_A(P) ((((g & 1) * 8 + ri) * (P) + (g >> 1) * 8) * 2)
#define OFF_B(P) ((((g >> 1) * 8 + ri) * (P) + (g & 1) * 8) * 2)

// ---------------- K0a: weight prep (fp16 QKV) --------------------------------
__global__ void prep_weights(const float* __restrict__ Wq, const float* __restrict__ Wk,
                             const float* __restrict__ Wv) {
    int i = blockIdx.x * blockDim.x + threadIdx.x;
    if (i < NC * NC) {
        g_Wqkv[i]               = __float2half_rn(Wq[i]);
        g_Wqkv[NC * NC + i]     = __float2half_rn(Wk[i]);
        g_Wqkv[2 * NC * NC + i] = __float2half_rn(Wv[i]);
    }
}

// ---------------- K0b: x[b][c][n] f32 -> g_xT[b][n][c] fp16 ------------------
__global__ void transpose_x(const float* __restrict__ x) {
    __shared__ float tile[32][33];
    int b = blockIdx.z, n0 = blockIdx.x * 32, c0 = blockIdx.y * 32;
    int tx = threadIdx.x, ty = threadIdx.y;
    const float* xb = x + (size_t)b * NC * NHW;
#pragma unroll
    for (int j = 0; j < 32; j += 8)
        tile[ty + j][tx] = xb[(size_t)(c0 + ty + j) * NHW + n0 + tx];
    __syncthreads();
    __half* o = g_xT + (size_t)b * NHW * NC;
#pragma unroll
    for (int j = 0; j < 32; j += 8)
        o[(size_t)(n0 + ty + j) * NC + c0 + tx] = __float2half_rn(tile[tx][ty + j]);
}

// ---------------- K1: QKV projection + phi (3-stage cp.async + ldmatrix) -----
#define PJ_STAGE 20480
#define PROJ_SMEM (3 * PJ_STAGE)
__global__ __launch_bounds__(256) void proj_kernel() {
    extern __shared__ __align__(16) char raw[];
    const int b = blockIdx.z, mt = blockIdx.y, nt = blockIdx.x;
    const int t = threadIdx.x, warp = t >> 5, lane = t & 31;
    const int wm = (warp >> 1) * 32, wn = (warp & 1) * 64;
    const int fr = lane >> 2, fc = (lane & 3) * 2;
    const int lr = t >> 2, lc = (t & 3) * 8;
    const int g = lane >> 3, ri = lane & 7;
    const uint32_t offA = OFF_A(40), offB = OFF_B(40);

    float acc[2][8][4] = {};
    const __half* Ag = g_Wqkv + (size_t)(mt * 128) * NC;
    const __half* Bg = g_xT + ((size_t)b * NHW + nt * 128) * NC;
    uint32_t raw_s = (uint32_t)__cvta_generic_to_shared(raw);

    auto issue = [&](int s, int k0) {
        uint32_t base = raw_s + s * PJ_STAGE;
#pragma unroll
        for (int i = 0; i < 2; i++) {
            int r = lr + i * 64;
            cpa16(base + (r * 40 + lc) * 2, Ag + (size_t)r * NC + k0 + lc);
            cpa16(base + 10240 + (r * 40 + lc) * 2, Bg + (size_t)r * NC + k0 + lc);
        }
    };

    issue(0, 0); CPA_COMMIT();
    issue(1, 32); CPA_COMMIT();
    for (int it = 0; it < 8; it++) {
        if (it < 6) CPA_WAIT1(); else CPA_WAIT0();
        __syncthreads();
        if (it < 6) { issue((it + 2) % 3, (it + 2) * 32); CPA_COMMIT(); }
        uint32_t sA_u = raw_s + (it % 3) * PJ_STAGE;
        uint32_t sB_u = sA_u + 10240;
#pragma unroll
        for (int ks = 0; ks < 32; ks += 16) {
            uint32_t a0[4], a1[4];
            LDSM4(a0, sA_u + (wm * 40 + ks) * 2 + offA);
            LDSM4(a1, sA_u + ((wm + 16) * 40 + ks) * 2 + offA);
#pragma unroll
            for (int p = 0; p < 4; p++) {
                uint32_t bb[4];
                LDSM4(bb, sB_u + ((wn + p * 16) * 40 + ks) * 2 + offB);
                mma16816(acc[0][2 * p], a0, bb);
                mma16816(acc[1][2 * p], a1, bb);
                mma16816(acc[0][2 * p + 1], a0, bb + 2);
                mma16816(acc[1][2 * p + 1], a1, bb + 2);
            }
        }
    }
    __syncthreads();

    if (mt == 2 || mt == 3) {
        __half* st = (__half*)raw;   // [128 n][136 pitch] staging (34816 B < PROJ_SMEM)
#pragma unroll
        for (int mi = 0; mi < 2; mi++)
#pragma unroll
            for (int ni = 0; ni < 8; ni++)
#pragma unroll
                for (int e = 0; e < 4; e++) {
                    int c = wm + mi * 16 + fr + (e >> 1) * 8;
                    int n = wn + ni * 8 + fc + (e & 1);
                    st[n * 136 + c] = __float2half_rn(phi_f(acc[mi][ni][e]));
                }
        __syncthreads();
        __half* dstb = g_phiKT + ((size_t)b * NHW + nt * 128) * NC + (mt - 2) * 128;
        for (int idx = t; idx < 128 * 16; idx += 256) {
            int nl = idx >> 4, ch = (idx & 15) * 8;
            *(uint4*)&dstb[(size_t)nl * NC + ch] = *(const uint4*)&st[nl * 136 + ch];
        }
    } else {
#pragma unroll
        for (int mi = 0; mi < 2; mi++) {
#pragma unroll
            for (int half = 0; half < 2; half++) {
                int gr = mt * 128 + wm + mi * 16 + fr + half * 8;
                int which = gr >> 8, cc = gr & 255;
                __half* dst = g_phi + (((size_t)b * 3 + which) * NC + cc) * NHW;
#pragma unroll
                for (int ni = 0; ni < 8; ni++) {
                    int gn = nt * 128 + wn + ni * 8 + fc;
                    *(__half2*)&dst[gn] = __floats2half2_rn(
                        phi_f(acc[mi][ni][half * 2 + 0]), phi_f(acc[mi][ni][half * 2 + 1]));
                }
            }
        }
    }
}

// ---------------- K2: qv split-K=8, 3-stage, K=32 chunks ---------------------
#define QV_STAGE 15360
#define QV_SMEM (3 * QV_STAGE)
__global__ __launch_bounds__(256) void qv_kernel() {
    extern __shared__ __align__(16) char raw[];     // 3 x (sA 128x40 | sB 64x40)
    const int dt = blockIdx.x, ct = blockIdx.y;
    const int b = blockIdx.z >> 3, ks = blockIdx.z & 7;
    const int t = threadIdx.x, warp = t >> 5, lane = t & 31;
    const int wm = (warp >> 1) * 32, wn = (warp & 1) * 32;
    const int fr = lane >> 2, fc = (lane & 3) * 2;
    const int lr = t >> 2, lc = (t & 3) * 8;
    const int g = lane >> 3, ri = lane & 7;
    const uint32_t offA = OFF_A(40), offB = OFF_B(40);

    float acc[2][4][4] = {};
    const __half* Ag = g_phi + (((size_t)b * 3 + 0) * NC + ct * 128) * NHW;
    const __half* Bg = g_phi + (((size_t)b * 3 + 2) * NC + dt * 64) * NHW;
    uint32_t raw_s = (uint32_t)__cvta_generic_to_shared(raw);

    auto issue = [&](int s, int k0) {
        uint32_t base = raw_s + s * QV_STAGE;
#pragma unroll
        for (int i = 0; i < 2; i++) {
            int r = lr + i * 64;
            cpa16(base + (r * 40 + lc) * 2, Ag + (size_t)r * NHW + k0 + lc);
        }
        cpa16(base + 10240 + (lr * 40 + lc) * 2, Bg + (size_t)lr * NHW + k0 + lc);
    };

    const int kbase = ks * 512;
    issue(0, kbase); CPA_COMMIT();
    issue(1, kbase + 32); CPA_COMMIT();
    for (int it = 0; it < 16; it++) {
        if (it < 14) CPA_WAIT1(); else CPA_WAIT0();
        __syncthreads();
        if (it < 14) { issue((it + 2) % 3, kbase + (it + 2) * 32); CPA_COMMIT(); }
        uint32_t sA_u = raw_s + (it % 3) * QV_STAGE;
        uint32_t sB_u = sA_u + 10240;
#pragma unroll
        for (int kk = 0; kk < 32; kk += 16) {
            uint32_t a0[4], a1[4];
            LDSM4(a0, sA_u + (wm * 40 + kk) * 2 + offA);
            LDSM4(a1, sA_u + ((wm + 16) * 40 + kk) * 2 + offA);
#pragma unroll
            for (int p = 0; p < 2; p++) {
                uint32_t bb[4];
                LDSM4(bb, sB_u + ((wn + p * 16) * 40 + kk) * 2 + offB);
                mma16816(acc[0][2 * p], a0, bb);
                mma16816(acc[1][2 * p], a1, bb);
                mma16816(acc[0][2 * p + 1], a0, bb + 2);
                mma16816(acc[1][2 * p + 1], a1, bb + 2);
            }
        }
    }

    float* dst = g_qvp + ((size_t)(ks * NB + b) * NC) * NC;
#pragma unroll
    for (int mi = 0; mi < 2; mi++)
#pragma unroll
        for (int ni = 0; ni < 4; ni++)
#pragma unroll
            for (int half = 0; half < 2; half++) {
                int c = ct * 128 + wm + mi * 16 + fr + half * 8;
                int d = dt * 64 + wn + ni * 8 + fc;
                float2 v;
                v.x = acc[mi][ni][half * 2 + 0];
                v.y = acc[mi][ni][half * 2 + 1];
                *(float2*)&dst[(size_t)c * NC + d] = v;
            }
}

// ---------------- K2.5: M = (Wo * sum_ks qvp)/16, fp16 output ----------------
__global__ __launch_bounds__(256) void mwo_kernel(const float* __restrict__ Wo) {
    __shared__ float sWo[16 * 256];
    const int b = blockIdx.x, o0 = blockIdx.y * 16;
    const int t = threadIdx.x;
#pragma unroll
    for (int i = 0; i < 16; i++)
        sWo[t + i * 256] = Wo[(size_t)(o0 + (t + i * 256) / 256) * NC + ((t + i * 256) & 255)];
    __syncthreads();

    const size_t stride = (size_t)NB * NC * NC;
    const float* q0 = g_qvp + (size_t)b * NC * NC;
    float acc[16] = {};
    for (int c = 0; c < NC; c++) {
        size_t off = (size_t)c * NC + t;
        float q = ((q0[off] + q0[stride + off]) + (q0[2 * stride + off] + q0[3 * stride + off]))
                + ((q0[4 * stride + off] + q0[5 * stride + off]) +
                   (q0[6 * stride + off] + q0[7 * stride + off]));
#pragma unroll
        for (int o = 0; o < 16; o++) acc[o] = fmaf(sWo[o * 256 + c], q, acc[o]);
    }
#pragma unroll
    for (int o = 0; o < 16; o++)
        g_M[((size_t)b * NC + o0 + o) * NC + t] = __float2half_rn(acc[o] * 0.0625f);
}

// ---------------- K3: out = 16 * (M * phiK^T) + bo (3-stage + ldmatrix) ------
#define OUT_SMEM (3 * PJ_STAGE)
__global__ __launch_bounds__(256) void out_kernel(const float* __restrict__ bo,
                                                  float* __restrict__ out) {
    extern __shared__ __align__(16) char raw[];
    const int b = blockIdx.z, ot = blockIdx.y, nt = blockIdx.x;
    const int t = threadIdx.x, warp = t >> 5, lane = t & 31;
    const int wm = (warp >> 1) * 32, wn = (warp & 1) * 64;
    const int fr = lane >> 2, fc = (lane & 3) * 2;
    const int lr = t >> 2, lc = (t & 3) * 8;
    const int g = lane >> 3, ri = lane & 7;
    const uint32_t offA = OFF_A(40), offB = OFF_B(40);

    float acc[2][8][4] = {};
    const __half* Ag = g_M + ((size_t)b * NC + ot * 128) * NC;
    const __half* Bg = g_phiKT + ((size_t)b * NHW + nt * 128) * NC;
    uint32_t raw_s = (uint32_t)__cvta_generic_to_shared(raw);

    auto issue = [&](int s, int k0) {
        uint32_t base = raw_s + s * PJ_STAGE;
#pragma unroll
        for (int i = 0; i < 2; i++) {
            int r = lr + i * 64;
            cpa16(base + (r * 40 + lc) * 2, Ag + (size_t)r * NC + k0 + lc);
            cpa16(base + 10240 + (r * 40 + lc) * 2, Bg + (size_t)r * NC + k0 + lc);
        }
    };

    issue(0, 0); CPA_COMMIT();
    issue(1, 32); CPA_COMMIT();
    for (int it = 0; it < 8; it++) {
        if (it < 6) CPA_WAIT1(); else CPA_WAIT0();
        __syncthreads();
        if (it < 6) { issue((it + 2) % 3, (it + 2) * 32); CPA_COMMIT(); }
        uint32_t sA_u = raw_s + (it % 3) * PJ_STAGE;
        uint32_t sB_u = sA_u + 10240;
#pragma unroll
        for (int ks = 0; ks < 32; ks += 16) {
            uint32_t a0[4], a1[4];
            LDSM4(a0, sA_u + (wm * 40 + ks) * 2 + offA);
            LDSM4(a1, sA_u + ((wm + 16) * 40 + ks) * 2 + offA);
#pragma unroll
            for (int p = 0; p < 4; p++) {
                uint32_t bb[4];
                LDSM4(bb, sB_u + ((wn + p * 16) * 40 + ks) * 2 + offB);
                mma16816(acc[0][2 * p], a0, bb);
                mma16816(acc[1][2 * p], a1, bb);
                mma16816(acc[0][2 * p + 1], a0, bb + 2);
                mma16816(acc[1][2 * p + 1], a1, bb + 2);
            }
        }
    }

#pragma unroll
    for (int mi = 0; mi < 2; mi++)
#pragma unroll
        for (int half = 0; half < 2; half++) {
            int o = ot * 128 + wm + mi * 16 + fr + half * 8;
            float bias = bo[o];
            float* orow = out + ((size_t)b * NC + o) * NHW;
#pragma unroll
            for (int ni = 0; ni < 8; ni++) {
                int gn = nt * 128 + wn + ni * 8 + fc;
                float2 v;
                v.x = acc[mi][ni][half * 2 + 0] * 16.0f + bias;
                v.y = acc[mi][ni][half * 2 + 1] * 16.0f + bias;
                *(float2*)&orow[gn] = v;
            }
        }
}

// ---------------- launch -----------------------------------------------------
extern "C" void kernel_launch(void* const* d_in, const int* in_sizes, int n_in,
                              void* d_out, int out_size) {
    (void)in_sizes; (void)n_in; (void)out_size;
    const float* x  = (const float*)d_in[0];
    const float* Wq = (const float*)d_in[1];
    const float* Wk = (const float*)d_in[2];
    const float* Wv = (const float*)d_in[3];
    const float* Wo = (const float*)d_in[4];
    const float* bo = (const float*)d_in[5];
    float* out = (float*)d_out;

    // Idempotent, capture-safe, no static guards.
    cudaFuncSetAttribute(proj_kernel, cudaFuncAttributeMaxDynamicSharedMemorySize, PROJ_SMEM);
    cudaFuncSetAttribute(qv_kernel, cudaFuncAttributeMaxDynamicSharedMemorySize, QV_SMEM);
    cudaFuncSetAttribute(out_kernel, cudaFuncAttributeMaxDynamicSharedMemorySize, OUT_SMEM);

    prep_weights<<<(NC * NC + 255) / 256, 256>>>(Wq, Wk, Wv);
    transpose_x<<<dim3(NHW / 32, NC / 32, NB), dim3(32, 8)>>>(x);
    proj_kernel<<<dim3(NHW / 128, 768 / 128, NB), 256, PROJ_SMEM>>>();
    qv_kernel<<<dim3(NC / 64, NC / 128, NB * 8), 256, QV_SMEM>>>();
    mwo_kernel<<<dim3(NB, 16), 256>>>(Wo);
    out_kernel<<<dim3(NHW / 128, NC / 128, NB), 256, OUT_SMEM>>>(bo, out);
}